// round 15
// baseline (speedup 1.0000x reference)
#include <cuda_runtime.h>
#include <cstdint>

#define NRAYS   1024
#define NSAMP   767
#define NC      64
#define DATADIM 28
#define NPROJ   224   // 8 * 28, tids 0..223 = warps 0-6
#define CHUNK   12
#define MAXS    768
#define GRIDB   592   // 148 SMs x 4 resident blocks -- one wave

__device__ int g_ray_counter;

// RN_f32(exp(-x)) for x >= 0 -- IDENTICAL to the passing R9..R14 version.
__device__ __forceinline__ float exp_neg_rn(float x) {
    if (x < 0.0625f) {
        double r = -(double)x;
        double e = 1.0 + r * (1.0 + r * (0.5 + r * (1.0 / 6.0 + r * (1.0 / 24.0 +
                   r * (1.0 / 120.0 + r * (1.0 / 720.0 + r * (1.0 / 5040.0)))))));
        return (float)e;
    }
    return (float)exp(-(double)x);
}

// Shade samples [s0+lane : s1 : stride]; arithmetic byte-identical to R11/R14.
__device__ __forceinline__ void shade_range(
    int s0, int s1, int lane, int stride, int cb,
    const short* s_run, const float* proj,
    float start, float ox, float oy, float oz,
    float dx, float dy, float dz, float dnorm,
    const float* shm,
    float* s_alpha, float (*s_g)[3], float* arow)
{
    const float RAD    = 1.3f;
    const float STEPF  = (float)(1.3 * 2.0 / 64.0 / 2.0 / 2.0);
    const float CLIPHI = (float)(1.0 - 1e-6);
    const float TWOR   = 2.6f;

    for (int s = s0 + lane; s <= s1; s += stride) {
        float ts = __fadd_rn(start, __fmul_rn((float)s, STEPF));
        float px = __fadd_rn(ox, __fmul_rn(ts, dx));
        float py = __fadd_rn(oy, __fmul_rn(ts, dy));
        float pz = __fadd_rn(oz, __fmul_rn(ts, dz));
        float qx = fminf(fmaxf(__fdiv_rn(__fadd_rn(px, RAD), TWOR), 0.0f), CLIPHI);
        float qy = fminf(fmaxf(__fdiv_rn(__fadd_rn(py, RAD), TWOR), 0.0f), CLIPHI);
        float qz = fminf(fmaxf(__fdiv_rn(__fadd_rn(pz, RAD), TWOR), 0.0f), CLIPHI);
        float pcx = __fmul_rn(qx, 64.0f);
        float pcy = __fmul_rn(qy, 64.0f);
        float pcz = __fmul_rn(qz, 64.0f);
        float fx = floorf(pcx), fy = floorf(pcy), fz = floorf(pcz);
        float lx = __fsub_rn(pcx, fx);
        float ly = __fsub_rn(pcy, fy);
        float lz = __fsub_rn(pcz, fz);

        float w0x, w1x, w0y, w1y, w0z, w1z;
        int i0x, i1x, i0y, i1y, i0z, i1z;
        {
            float u = __fsub_rn(__fmul_rn(lx, 2.0f), 0.5f);
            float fl = floorf(u); float t = __fsub_rn(u, fl);
            int ii = (int)fl;
            i0x = min(max(ii, 0), 1); i1x = min(max(ii + 1, 0), 1);
            w0x = __fsub_rn(1.0f, t); w1x = t;
        }
        {
            float u = __fsub_rn(__fmul_rn(ly, 2.0f), 0.5f);
            float fl = floorf(u); float t = __fsub_rn(u, fl);
            int ii = (int)fl;
            i0y = min(max(ii, 0), 1); i1y = min(max(ii + 1, 0), 1);
            w0y = __fsub_rn(1.0f, t); w1y = t;
        }
        {
            float u = __fsub_rn(__fmul_rn(lz, 2.0f), 0.5f);
            float fl = floorf(u); float t = __fsub_rn(u, fl);
            int ii = (int)fl;
            i0z = min(max(ii, 0), 1); i1z = min(max(ii + 1, 0), 1);
            w0z = __fsub_rn(1.0f, t); w1z = t;
        }

        float w8[8]; int off8[8];
        {
            int idx = 0;
            #pragma unroll
            for (int kx = 0; kx < 2; kx++) {
                float wx = kx ? w1x : w0x;
                int   ix = kx ? i1x : i0x;
                #pragma unroll
                for (int ky = 0; ky < 2; ky++) {
                    float wxy = __fmul_rn(wx, ky ? w1y : w0y);
                    int   iy  = ix * 2 + (ky ? i1y : i0y);
                    #pragma unroll
                    for (int kz = 0; kz < 2; kz++) {
                        w8[idx]   = __fmul_rn(wxy, kz ? w1z : w0z);
                        off8[idx] = (iy * 2 + (kz ? i1z : i0z)) * DATADIM;
                        idx++;
                    }
                }
            }
        }

        const float* prow = proj + (s_run[s] - cb) * (8 * DATADIM);
        float r0 = 0.0f, r1 = 0.0f, r2 = 0.0f, sig_o = 0.0f;
        #pragma unroll
        for (int dg = 0; dg < 7; dg++) {
            float o0 = 0.0f, o1 = 0.0f, o2 = 0.0f, o3 = 0.0f;
            #pragma unroll
            for (int k = 0; k < 8; k++) {
                const float4 p = *(const float4*)(prow + off8[k] + dg * 4);
                o0 = __fadd_rn(o0, __fmul_rn(w8[k], p.x));
                o1 = __fadd_rn(o1, __fmul_rn(w8[k], p.y));
                o2 = __fadd_rn(o2, __fmul_rn(w8[k], p.z));
                o3 = __fadd_rn(o3, __fmul_rn(w8[k], p.w));
            }
            const int d0 = dg * 4;
            float ov[4] = {o0, o1, o2, o3};
            #pragma unroll
            for (int j = 0; j < 4; j++) {
                const int d = d0 + j;
                if (d < 9)        r0 = fmaf(ov[j], shm[d], r0);
                else if (d < 18)  r1 = fmaf(ov[j], shm[d - 9], r1);
                else if (d < 27)  r2 = fmaf(ov[j], shm[d - 18], r2);
                else              sig_o = ov[j];
            }
        }

        // alpha path -- bit-identical to R9..R14
        float sigma = fmaxf(sig_o, 0.0f);
        float ts1   = __fadd_rn(start, __fmul_rn((float)(s + 1), STEPF));
        float dist  = __fmul_rn(__fsub_rn(ts1, ts), dnorm);
        float x     = __fmul_rn(sigma, dist);
        float e     = exp_neg_rn(x);
        float alpha = __fsub_rn(1.0f, e);
        s_alpha[s] = alpha;
        arow[s]    = alpha;

        s_g[s][0] = 1.0f / (1.0f + expf(-r0));
        s_g[s][1] = 1.0f / (1.0f + expf(-r1));
        s_g[s][2] = 1.0f / (1.0f + expf(-r2));
    }
}

__global__ void __launch_bounds__(256, 4) plenoxel_kernel(
    const float* __restrict__ rays_o,
    const float* __restrict__ rays_d,
    const float* __restrict__ grid,
    const float* __restrict__ atoms,
    float* __restrict__ out)
{
    const float RAD    = 1.3f;
    const float STEPF  = (float)(1.3 * 2.0 / 64.0 / 2.0 / 2.0);
    const float CLIPHI = (float)(1.0 - 1e-6);
    const float TWOR   = 2.6f;

    const int tid = threadIdx.x;

    __shared__ __align__(16) float s_coeff[CHUNK][NC];           // 3 KB
    __shared__ __align__(16) float s_proj[2][CHUNK][8][DATADIM]; // 21 KB, ping-pong
    __shared__ int   s_clin[MAXS];       // 3 KB (aliased as s_ab after phase 3)
    __shared__ short s_run[MAXS];        // 1.5 KB
    __shared__ short s_runstart[MAXS];   // 1.5 KB
    __shared__ int   s_runclin[MAXS];    // 3 KB
    __shared__ float s_alpha[MAXS];      // 3 KB
    __shared__ float s_g[MAXS][3];       // 9 KB
    __shared__ float s_red[8][8];
    __shared__ unsigned s_bits[24];
    __shared__ int   s_cnt[24], s_cbase[24];
    __shared__ int   s_slo, s_shi, s_nruns, s_ray;

    float* s_ab = (float*)s_clin;        // s_clin dead after RLE

    float* out_rgb   = out;                              // [1024][3]
    float* out_alpha = out + NRAYS * 3;                  // [1024][767]
    float* out_depth = out + NRAYS * 3 + NRAYS * NSAMP;  // [1024]

    // ---- persistent work-stealing loop over rays ----
    for (;;) {
        if (tid == 0) s_ray = atomicAdd(&g_ray_counter, 1);
        __syncthreads();
        const int ray = s_ray;              // block-uniform
        if (ray >= NRAYS) break;

        float* arow = out_alpha + ray * NSAMP;

        // ---- per-ray data (block-uniform, all threads) ----
        const float ox = rays_o[ray * 3 + 0];
        const float oy = rays_o[ray * 3 + 1];
        const float oz = rays_o[ray * 3 + 2];
        const float dx = rays_d[ray * 3 + 0];
        const float dy = rays_d[ray * 3 + 1];
        const float dz = rays_d[ray * 3 + 2];

        float start;
        {
            float ax = fminf(__fdiv_rn(__fsub_rn(RAD, ox), dx), __fdiv_rn(__fsub_rn(-RAD, ox), dx));
            float ay = fminf(__fdiv_rn(__fsub_rn(RAD, oy), dy), __fdiv_rn(__fsub_rn(-RAD, oy), dy));
            float az = fminf(__fdiv_rn(__fsub_rn(RAD, oz), dz), __fdiv_rn(__fsub_rn(-RAD, oz), dz));
            start = fmaxf(fmaxf(ax, ay), az);
        }
        const float dnorm = sqrtf(__fadd_rn(__fadd_rn(__fmul_rn(dx, dx), __fmul_rn(dy, dy)),
                                            __fmul_rn(dz, dz)));

        float shm[9];
        {
            float x = __fdiv_rn(dx, dnorm), y = __fdiv_rn(dy, dnorm), z = __fdiv_rn(dz, dnorm);
            shm[0] = 0.28209479177387814f;
            shm[1] = -0.4886025119029199f * y;
            shm[2] =  0.4886025119029199f * z;
            shm[3] = -0.4886025119029199f * x;
            shm[4] =  1.0925484305920792f * x * y;
            shm[5] = -1.0925484305920792f * y * z;
            shm[6] =  0.31539156525252005f * (2.0f * z * z - x * x - y * y);
            shm[7] = -1.0925484305920792f * x * z;
            shm[8] =  0.5462742152960396f * (x * x - y * y);
        }

        // ---- Phase 1+2: mask interval + per-sample cell ids (parallel) ----
        if (tid == 0) { s_slo = 0x7FFFFFFF; s_shi = -1; }
        __syncthreads();

        for (int s = tid; s < NSAMP; s += 256) {
            float ts = __fadd_rn(start, __fmul_rn((float)s, STEPF));
            float px = __fadd_rn(ox, __fmul_rn(ts, dx));
            float py = __fadd_rn(oy, __fmul_rn(ts, dy));
            float pz = __fadd_rn(oz, __fmul_rn(ts, dz));
            bool mask = (px > -RAD) && (px < RAD) &&
                        (py > -RAD) && (py < RAD) &&
                        (pz > -RAD) && (pz < RAD);
            if (mask) {
                atomicMin(&s_slo, s);
                atomicMax(&s_shi, s);
                float qx = fminf(fmaxf(__fdiv_rn(__fadd_rn(px, RAD), TWOR), 0.0f), CLIPHI);
                float qy = fminf(fmaxf(__fdiv_rn(__fadd_rn(py, RAD), TWOR), 0.0f), CLIPHI);
                float qz = fminf(fmaxf(__fdiv_rn(__fadd_rn(pz, RAD), TWOR), 0.0f), CLIPHI);
                int cx = (int)floorf(__fmul_rn(qx, 64.0f));
                int cy = (int)floorf(__fmul_rn(qy, 64.0f));
                int cz = (int)floorf(__fmul_rn(qz, 64.0f));
                s_clin[s] = (cx * 64 + cy) * 64 + cz;
            }
        }
        __syncthreads();

        const int slo = s_slo, shi = s_shi;
        const int L = (shi >= slo) ? (shi - slo + 1) : 0;
        const int nchunks32 = (L + 31) >> 5;

        // ---- Phase 3: parallel run-length encode via warp ballots ----
        for (int i = tid; i < nchunks32 * 32; i += 256) {
            int lane = i & 31, chunk = i >> 5;
            bool flag = false;
            if (i < L) {
                int s = slo + i;
                flag = (i == 0) || (s_clin[s] != s_clin[s - 1]);
            }
            unsigned b = __ballot_sync(0xFFFFFFFFu, flag);
            if (lane == 0) { s_bits[chunk] = b; s_cnt[chunk] = __popc(b); }
        }
        __syncthreads();
        if (tid == 0) {
            int acc = 0;
            for (int c = 0; c < nchunks32; c++) { s_cbase[c] = acc; acc += s_cnt[c]; }
            s_nruns = acc;
        }
        __syncthreads();
        for (int i = tid; i < L; i += 256) {
            int s = slo + i;
            int lane = i & 31, chunk = i >> 5;
            unsigned b = s_bits[chunk];
            int idx = s_cbase[chunk] + __popc(b & ((1u << lane) - 1u));
            int flag = (b >> lane) & 1u;
            if (flag) { s_runclin[idx] = s_clin[s]; s_runstart[idx] = (short)s; }
            s_run[s] = (short)(idx + flag - 1);
        }
        __syncthreads();   // also: last read of s_clin before s_ab aliasing

        const int nruns  = s_nruns;
        const int nloops = (nruns + CHUNK - 1) / CHUNK;

        // ---- Phase 4: warp-specialized pipeline ----
        // warps 0-6: stage coeff -> project chunk c into s_proj[c&1]
        // warp 7:    shade chunk c-1 from s_proj[(c-1)&1]
        float pre[5];
        if (tid < NPROJ && nloops > 0) {
            const int nr0 = min(CHUNK, nruns);
            #pragma unroll
            for (int j = 0; j < 5; j++) {
                int idx = tid + j * NPROJ;
                if (idx < nr0 * NC)
                    pre[j] = grid[(long long)s_runclin[idx >> 6] * NC + (idx & 63)];
            }
        }

        const int pf = tid / DATADIM;
        const int pd = tid - pf * DATADIM;

        for (int c = 0; c < nloops; c++) {
            const int cb = c * CHUNK;
            const int nr_c = min(CHUNK, nruns - cb);

            if (tid < NPROJ) {
                #pragma unroll
                for (int j = 0; j < 5; j++) {
                    int idx = tid + j * NPROJ;
                    if (idx < nr_c * NC)
                        s_coeff[idx >> 6][idx & 63] = pre[j];
                }
                asm volatile("bar.sync 1, 224;" ::: "memory");

                const int nb = cb + CHUNK;
                if (nb < nruns) {
                    const int nrn = min(CHUNK, nruns - nb);
                    #pragma unroll
                    for (int j = 0; j < 5; j++) {
                        int idx = tid + j * NPROJ;
                        if (idx < nrn * NC)
                            pre[j] = grid[(long long)s_runclin[nb + (idx >> 6)] * NC + (idx & 63)];
                    }
                }

                // projection: scalar a=0..63 sequential chain per run
                const float* __restrict__ acol = atoms + (pf * NC) * DATADIM + pd;
                float accv[CHUNK];
                #pragma unroll
                for (int r = 0; r < CHUNK; r++) accv[r] = 0.0f;
                #pragma unroll 4
                for (int a4 = 0; a4 < NC / 4; a4++) {
                    float av0 = __ldg(acol + (a4 * 4 + 0) * DATADIM);
                    float av1 = __ldg(acol + (a4 * 4 + 1) * DATADIM);
                    float av2 = __ldg(acol + (a4 * 4 + 2) * DATADIM);
                    float av3 = __ldg(acol + (a4 * 4 + 3) * DATADIM);
                    #pragma unroll
                    for (int r = 0; r < CHUNK; r++) {
                        float4 cc = *(const float4*)&s_coeff[r][a4 * 4];
                        accv[r] = fmaf(cc.x, av0, accv[r]);
                        accv[r] = fmaf(cc.y, av1, accv[r]);
                        accv[r] = fmaf(cc.z, av2, accv[r]);
                        accv[r] = fmaf(cc.w, av3, accv[r]);
                    }
                }
                #pragma unroll
                for (int r = 0; r < CHUNK; r++)
                    if (r < nr_c) s_proj[c & 1][r][pf][pd] = accv[r];
            } else if (c > 0) {
                const int cbp   = cb - CHUNK;
                const int cs_lo = s_runstart[cbp];
                const int cs_hi = s_runstart[cbp + CHUNK] - 1;
                shade_range(cs_lo, cs_hi, tid - NPROJ, 32, cbp,
                            s_run, &s_proj[(c - 1) & 1][0][0][0],
                            start, ox, oy, oz, dx, dy, dz, dnorm, shm,
                            s_alpha, s_g, arow);
            }
            __syncthreads();   // closes s_proj WAR + s_coeff WAR
        }

        // epilogue: shade the last chunk with ALL threads
        if (nloops > 0) {
            const int cbl   = (nloops - 1) * CHUNK;
            const int cs_lo = s_runstart[cbl];
            shade_range(cs_lo, shi, tid, 256, cbl,
                        s_run, &s_proj[(nloops - 1) & 1][0][0][0],
                        start, ox, oy, oz, dx, dy, dz, dnorm, shm,
                        s_alpha, s_g, arow);
        }
        __syncthreads();

        // ---- Phase 5: serial transmittance scan (thread 0, bit-exact) ----
        if (tid == 0 && L > 0) {
            float T = 1.0f;
            for (int s = slo; s <= shi; s++) {
                float a  = s_alpha[s];
                float ab = a * T;
                s_ab[s] = ab;
                T = __fmul_rn(T, __fadd_rn(__fsub_rn(1.0f, a), 1e-10f));
            }
        }
        __syncthreads();

        // ---- Phase 6: parallel reduction of comp / acc / depth ----
        float c0 = 0.0f, c1 = 0.0f, c2 = 0.0f, pacc = 0.0f, pdep = 0.0f;
        if (L > 0) {
            for (int s = slo + tid; s <= shi; s += 256) {
                float ab = s_ab[s];
                float ts = __fadd_rn(start, __fmul_rn((float)s, STEPF));
                c0   = fmaf(ab, s_g[s][0], c0);
                c1   = fmaf(ab, s_g[s][1], c1);
                c2   = fmaf(ab, s_g[s][2], c2);
                pacc += ab;
                pdep = fmaf(ab, ts, pdep);
            }
        }
        {
            const unsigned m = 0xFFFFFFFFu;
            #pragma unroll
            for (int o = 16; o > 0; o >>= 1) {
                c0   += __shfl_down_sync(m, c0, o);
                c1   += __shfl_down_sync(m, c1, o);
                c2   += __shfl_down_sync(m, c2, o);
                pacc += __shfl_down_sync(m, pacc, o);
                pdep += __shfl_down_sync(m, pdep, o);
            }
            int wd = tid >> 5, lane = tid & 31;
            if (lane == 0) {
                s_red[wd][0] = c0; s_red[wd][1] = c1; s_red[wd][2] = c2;
                s_red[wd][3] = pacc; s_red[wd][4] = pdep;
            }
            __syncthreads();
            if (tid == 0) {
                float t0 = 0, t1 = 0, t2 = 0, ta = 0, td = 0;
                #pragma unroll
                for (int w = 0; w < 8; w++) {
                    t0 += s_red[w][0]; t1 += s_red[w][1]; t2 += s_red[w][2];
                    ta += s_red[w][3]; td += s_red[w][4];
                }
                out_depth[ray] = td;
                float bg = __fsub_rn(1.0f, ta);
                out_rgb[ray * 3 + 0] = t0 + bg;
                out_rgb[ray * 3 + 1] = t1 + bg;
                out_rgb[ray * 3 + 2] = t2 + bg;
            }
        }

        // ---- Phase 7: zero masked alphas (parallel, coalesced) ----
        for (int s = tid; s < NSAMP; s += 256)
            if (s < slo || s > shi) arow[s] = 0.0f;

        __syncthreads();   // seal smem reuse before next ray
    }
}

extern "C" void kernel_launch(void* const* d_in, const int* in_sizes, int n_in,
                              void* d_out, int out_size) {
    const float* rays_o = (const float*)d_in[0];
    const float* rays_d = (const float*)d_in[1];
    const float* grid   = (const float*)d_in[2];
    const float* atoms  = (const float*)d_in[3];
    // d_in[4] = grid_id (unused)

    void* ctr_addr = nullptr;
    cudaGetSymbolAddress(&ctr_addr, g_ray_counter);
    cudaMemsetAsync(ctr_addr, 0, sizeof(int));
    plenoxel_kernel<<<GRIDB, 256>>>(rays_o, rays_d, grid, atoms, (float*)d_out);
}

// round 16
// speedup vs baseline: 1.0295x; 1.0295x over previous
#include <cuda_runtime.h>
#include <cstdint>

#define NRAYS   1024
#define NSAMP   767
#define NC      64
#define DATADIM 28
#define NPROJ   224   // 8 * 28, tids 0..223 = warps 0-6
#define CHUNK   12
#define MAXS    768
#define RUNSTRIDE (8 * DATADIM + 4)   // 228 floats: banks shift 4/run, kills conflicts

// RN_f32(exp(-x)) for x >= 0 -- IDENTICAL to the passing R9..R15 version.
__device__ __forceinline__ float exp_neg_rn(float x) {
    if (x < 0.0625f) {
        double r = -(double)x;
        double e = 1.0 + r * (1.0 + r * (0.5 + r * (1.0 / 6.0 + r * (1.0 / 24.0 +
                   r * (1.0 / 120.0 + r * (1.0 / 720.0 + r * (1.0 / 5040.0)))))));
        return (float)e;
    }
    return (float)exp(-(double)x);
}

// Shade samples [s0+lane : s1 : stride]; arithmetic byte-identical to R11/R14.
__device__ __forceinline__ void shade_range(
    int s0, int s1, int lane, int stride, int cb,
    const short* s_run, const float* proj,
    float start, float ox, float oy, float oz,
    float dx, float dy, float dz, float dnorm,
    const float* shm,
    float* s_alpha, float (*s_g)[3], float* arow)
{
    const float RAD    = 1.3f;
    const float STEPF  = (float)(1.3 * 2.0 / 64.0 / 2.0 / 2.0);
    const float CLIPHI = (float)(1.0 - 1e-6);
    const float TWOR   = 2.6f;

    for (int s = s0 + lane; s <= s1; s += stride) {
        float ts = __fadd_rn(start, __fmul_rn((float)s, STEPF));
        float px = __fadd_rn(ox, __fmul_rn(ts, dx));
        float py = __fadd_rn(oy, __fmul_rn(ts, dy));
        float pz = __fadd_rn(oz, __fmul_rn(ts, dz));
        float qx = fminf(fmaxf(__fdiv_rn(__fadd_rn(px, RAD), TWOR), 0.0f), CLIPHI);
        float qy = fminf(fmaxf(__fdiv_rn(__fadd_rn(py, RAD), TWOR), 0.0f), CLIPHI);
        float qz = fminf(fmaxf(__fdiv_rn(__fadd_rn(pz, RAD), TWOR), 0.0f), CLIPHI);
        float pcx = __fmul_rn(qx, 64.0f);
        float pcy = __fmul_rn(qy, 64.0f);
        float pcz = __fmul_rn(qz, 64.0f);
        float fx = floorf(pcx), fy = floorf(pcy), fz = floorf(pcz);
        float lx = __fsub_rn(pcx, fx);
        float ly = __fsub_rn(pcy, fy);
        float lz = __fsub_rn(pcz, fz);

        float w0x, w1x, w0y, w1y, w0z, w1z;
        int i0x, i1x, i0y, i1y, i0z, i1z;
        {
            float u = __fsub_rn(__fmul_rn(lx, 2.0f), 0.5f);
            float fl = floorf(u); float t = __fsub_rn(u, fl);
            int ii = (int)fl;
            i0x = min(max(ii, 0), 1); i1x = min(max(ii + 1, 0), 1);
            w0x = __fsub_rn(1.0f, t); w1x = t;
        }
        {
            float u = __fsub_rn(__fmul_rn(ly, 2.0f), 0.5f);
            float fl = floorf(u); float t = __fsub_rn(u, fl);
            int ii = (int)fl;
            i0y = min(max(ii, 0), 1); i1y = min(max(ii + 1, 0), 1);
            w0y = __fsub_rn(1.0f, t); w1y = t;
        }
        {
            float u = __fsub_rn(__fmul_rn(lz, 2.0f), 0.5f);
            float fl = floorf(u); float t = __fsub_rn(u, fl);
            int ii = (int)fl;
            i0z = min(max(ii, 0), 1); i1z = min(max(ii + 1, 0), 1);
            w0z = __fsub_rn(1.0f, t); w1z = t;
        }

        float w8[8]; int off8[8];
        {
            int idx = 0;
            #pragma unroll
            for (int kx = 0; kx < 2; kx++) {
                float wx = kx ? w1x : w0x;
                int   ix = kx ? i1x : i0x;
                #pragma unroll
                for (int ky = 0; ky < 2; ky++) {
                    float wxy = __fmul_rn(wx, ky ? w1y : w0y);
                    int   iy  = ix * 2 + (ky ? i1y : i0y);
                    #pragma unroll
                    for (int kz = 0; kz < 2; kz++) {
                        w8[idx]   = __fmul_rn(wxy, kz ? w1z : w0z);
                        off8[idx] = (iy * 2 + (kz ? i1z : i0z)) * DATADIM;
                        idx++;
                    }
                }
            }
        }

        const float* prow = proj + (s_run[s] - cb) * RUNSTRIDE;
        float r0 = 0.0f, r1 = 0.0f, r2 = 0.0f, sig_o = 0.0f;
        #pragma unroll
        for (int dg = 0; dg < 7; dg++) {
            float o0 = 0.0f, o1 = 0.0f, o2 = 0.0f, o3 = 0.0f;
            #pragma unroll
            for (int k = 0; k < 8; k++) {
                const float4 p = *(const float4*)(prow + off8[k] + dg * 4);
                o0 = __fadd_rn(o0, __fmul_rn(w8[k], p.x));
                o1 = __fadd_rn(o1, __fmul_rn(w8[k], p.y));
                o2 = __fadd_rn(o2, __fmul_rn(w8[k], p.z));
                o3 = __fadd_rn(o3, __fmul_rn(w8[k], p.w));
            }
            const int d0 = dg * 4;
            float ov[4] = {o0, o1, o2, o3};
            #pragma unroll
            for (int j = 0; j < 4; j++) {
                const int d = d0 + j;
                if (d < 9)        r0 = fmaf(ov[j], shm[d], r0);
                else if (d < 18)  r1 = fmaf(ov[j], shm[d - 9], r1);
                else if (d < 27)  r2 = fmaf(ov[j], shm[d - 18], r2);
                else              sig_o = ov[j];
            }
        }

        // alpha path -- bit-identical to R9..R15
        float sigma = fmaxf(sig_o, 0.0f);
        float ts1   = __fadd_rn(start, __fmul_rn((float)(s + 1), STEPF));
        float dist  = __fmul_rn(__fsub_rn(ts1, ts), dnorm);
        float x     = __fmul_rn(sigma, dist);
        float e     = exp_neg_rn(x);
        float alpha = __fsub_rn(1.0f, e);
        s_alpha[s] = alpha;
        arow[s]    = alpha;

        s_g[s][0] = 1.0f / (1.0f + expf(-r0));
        s_g[s][1] = 1.0f / (1.0f + expf(-r1));
        s_g[s][2] = 1.0f / (1.0f + expf(-r2));
    }
}

__global__ void __launch_bounds__(256, 4) plenoxel_kernel(
    const float* __restrict__ rays_o,
    const float* __restrict__ rays_d,
    const float* __restrict__ grid,
    const float* __restrict__ atoms,
    float* __restrict__ out)
{
    const float RAD    = 1.3f;
    const float STEPF  = (float)(1.3 * 2.0 / 64.0 / 2.0 / 2.0);
    const float CLIPHI = (float)(1.0 - 1e-6);
    const float TWOR   = 2.6f;

    const int ray = blockIdx.x;
    const int tid = threadIdx.x;
    if (ray >= NRAYS) return;

    __shared__ __align__(16) float s_coeff[CHUNK][NC];        // 3 KB
    __shared__ __align__(16) float s_proj[2][CHUNK][RUNSTRIDE]; // 21.9 KB, ping-pong
    __shared__ int   s_clin[MAXS];       // 3 KB (aliased as s_ab after phase 3)
    __shared__ short s_run[MAXS];        // 1.5 KB
    __shared__ short s_runstart[MAXS];   // 1.5 KB
    __shared__ int   s_runclin[MAXS];    // 3 KB
    __shared__ float s_alpha[MAXS];      // 3 KB
    __shared__ float s_g[MAXS][3];       // 9 KB
    __shared__ float s_red[8][8];
    __shared__ unsigned s_bits[24];
    __shared__ int   s_cnt[24], s_cbase[24];
    __shared__ int   s_slo, s_shi, s_nruns;

    float* s_ab = (float*)s_clin;        // s_clin dead after RLE

    float* out_rgb   = out;                              // [1024][3]
    float* out_alpha = out + NRAYS * 3;                  // [1024][767]
    float* out_depth = out + NRAYS * 3 + NRAYS * NSAMP;  // [1024]
    float* arow      = out_alpha + ray * NSAMP;

    // ---- per-ray data (block-uniform, all threads) ----
    const float ox = rays_o[ray * 3 + 0];
    const float oy = rays_o[ray * 3 + 1];
    const float oz = rays_o[ray * 3 + 2];
    const float dx = rays_d[ray * 3 + 0];
    const float dy = rays_d[ray * 3 + 1];
    const float dz = rays_d[ray * 3 + 2];

    float start;
    {
        float ax = fminf(__fdiv_rn(__fsub_rn(RAD, ox), dx), __fdiv_rn(__fsub_rn(-RAD, ox), dx));
        float ay = fminf(__fdiv_rn(__fsub_rn(RAD, oy), dy), __fdiv_rn(__fsub_rn(-RAD, oy), dy));
        float az = fminf(__fdiv_rn(__fsub_rn(RAD, oz), dz), __fdiv_rn(__fsub_rn(-RAD, oz), dz));
        start = fmaxf(fmaxf(ax, ay), az);
    }
    const float dnorm = sqrtf(__fadd_rn(__fadd_rn(__fmul_rn(dx, dx), __fmul_rn(dy, dy)),
                                        __fmul_rn(dz, dz)));

    // SH basis (all threads -- epilogue shading uses any thread)
    float shm[9];
    {
        float x = __fdiv_rn(dx, dnorm), y = __fdiv_rn(dy, dnorm), z = __fdiv_rn(dz, dnorm);
        shm[0] = 0.28209479177387814f;
        shm[1] = -0.4886025119029199f * y;
        shm[2] =  0.4886025119029199f * z;
        shm[3] = -0.4886025119029199f * x;
        shm[4] =  1.0925484305920792f * x * y;
        shm[5] = -1.0925484305920792f * y * z;
        shm[6] =  0.31539156525252005f * (2.0f * z * z - x * x - y * y);
        shm[7] = -1.0925484305920792f * x * z;
        shm[8] =  0.5462742152960396f * (x * x - y * y);
    }

    // ---- Phase 1+2: mask interval + per-sample cell ids (parallel) ----
    if (tid == 0) { s_slo = 0x7FFFFFFF; s_shi = -1; }
    __syncthreads();

    for (int s = tid; s < NSAMP; s += 256) {
        float ts = __fadd_rn(start, __fmul_rn((float)s, STEPF));
        float px = __fadd_rn(ox, __fmul_rn(ts, dx));
        float py = __fadd_rn(oy, __fmul_rn(ts, dy));
        float pz = __fadd_rn(oz, __fmul_rn(ts, dz));
        bool mask = (px > -RAD) && (px < RAD) &&
                    (py > -RAD) && (py < RAD) &&
                    (pz > -RAD) && (pz < RAD);
        if (mask) {
            atomicMin(&s_slo, s);
            atomicMax(&s_shi, s);
            float qx = fminf(fmaxf(__fdiv_rn(__fadd_rn(px, RAD), TWOR), 0.0f), CLIPHI);
            float qy = fminf(fmaxf(__fdiv_rn(__fadd_rn(py, RAD), TWOR), 0.0f), CLIPHI);
            float qz = fminf(fmaxf(__fdiv_rn(__fadd_rn(pz, RAD), TWOR), 0.0f), CLIPHI);
            int cx = (int)floorf(__fmul_rn(qx, 64.0f));
            int cy = (int)floorf(__fmul_rn(qy, 64.0f));
            int cz = (int)floorf(__fmul_rn(qz, 64.0f));
            s_clin[s] = (cx * 64 + cy) * 64 + cz;
        }
    }
    __syncthreads();

    const int slo = s_slo, shi = s_shi;
    const int L = (shi >= slo) ? (shi - slo + 1) : 0;
    const int nchunks32 = (L + 31) >> 5;

    // ---- Phase 3: parallel run-length encode via warp ballots ----
    for (int i = tid; i < nchunks32 * 32; i += 256) {
        int lane = i & 31, chunk = i >> 5;
        bool flag = false;
        if (i < L) {
            int s = slo + i;
            flag = (i == 0) || (s_clin[s] != s_clin[s - 1]);
        }
        unsigned b = __ballot_sync(0xFFFFFFFFu, flag);
        if (lane == 0) { s_bits[chunk] = b; s_cnt[chunk] = __popc(b); }
    }
    __syncthreads();
    if (tid == 0) {
        int acc = 0;
        for (int c = 0; c < nchunks32; c++) { s_cbase[c] = acc; acc += s_cnt[c]; }
        s_nruns = acc;
    }
    __syncthreads();
    for (int i = tid; i < L; i += 256) {
        int s = slo + i;
        int lane = i & 31, chunk = i >> 5;
        unsigned b = s_bits[chunk];
        int idx = s_cbase[chunk] + __popc(b & ((1u << lane) - 1u));
        int flag = (b >> lane) & 1u;
        if (flag) { s_runclin[idx] = s_clin[s]; s_runstart[idx] = (short)s; }
        s_run[s] = (short)(idx + flag - 1);
    }
    __syncthreads();   // also: last read of s_clin before s_ab aliasing

    const int nruns  = s_nruns;
    const int nloops = (nruns + CHUNK - 1) / CHUNK;

    // ---- Phase 4: warp-specialized pipeline ----
    // warps 0-6 (tids 0..223): stage coeff -> project chunk c into s_proj[c&1]
    // warp 7   (tids 224..255): shade chunk c-1 from s_proj[(c-1)&1]
    float pre[5];
    if (tid < NPROJ && nloops > 0) {
        const int nr0 = min(CHUNK, nruns);
        #pragma unroll
        for (int j = 0; j < 5; j++) {
            int idx = tid + j * NPROJ;
            if (idx < nr0 * NC)
                pre[j] = grid[(long long)s_runclin[idx >> 6] * NC + (idx & 63)];
        }
    }

    const int pf = tid / DATADIM;
    const int pd = tid - pf * DATADIM;

    for (int c = 0; c < nloops; c++) {
        const int cb = c * CHUNK;
        const int nr_c = min(CHUNK, nruns - cb);

        if (tid < NPROJ) {
            // commit prefetched coeff
            #pragma unroll
            for (int j = 0; j < 5; j++) {
                int idx = tid + j * NPROJ;
                if (idx < nr_c * NC)
                    s_coeff[idx >> 6][idx & 63] = pre[j];
            }
            asm volatile("bar.sync 1, 224;" ::: "memory");

            // prefetch next chunk (overlaps projection)
            const int nb = cb + CHUNK;
            if (nb < nruns) {
                const int nrn = min(CHUNK, nruns - nb);
                #pragma unroll
                for (int j = 0; j < 5; j++) {
                    int idx = tid + j * NPROJ;
                    if (idx < nrn * NC)
                        pre[j] = grid[(long long)s_runclin[nb + (idx >> 6)] * NC + (idx & 63)];
                }
            }

            // projection: scalar a=0..63 sequential chain per run (bit-identical
            // sigma) into buffer c&1
            const float* __restrict__ acol = atoms + (pf * NC) * DATADIM + pd;
            float accv[CHUNK];
            #pragma unroll
            for (int r = 0; r < CHUNK; r++) accv[r] = 0.0f;
            #pragma unroll 4
            for (int a4 = 0; a4 < NC / 4; a4++) {
                float av0 = __ldg(acol + (a4 * 4 + 0) * DATADIM);
                float av1 = __ldg(acol + (a4 * 4 + 1) * DATADIM);
                float av2 = __ldg(acol + (a4 * 4 + 2) * DATADIM);
                float av3 = __ldg(acol + (a4 * 4 + 3) * DATADIM);
                #pragma unroll
                for (int r = 0; r < CHUNK; r++) {
                    float4 cc = *(const float4*)&s_coeff[r][a4 * 4];
                    accv[r] = fmaf(cc.x, av0, accv[r]);
                    accv[r] = fmaf(cc.y, av1, accv[r]);
                    accv[r] = fmaf(cc.z, av2, accv[r]);
                    accv[r] = fmaf(cc.w, av3, accv[r]);
                }
            }
            #pragma unroll
            for (int r = 0; r < CHUNK; r++)
                if (r < nr_c) s_proj[c & 1][r][pf * DATADIM + pd] = accv[r];
        } else if (c > 0) {
            // warp 7: shade the previous chunk (never the last one here)
            const int cbp   = cb - CHUNK;
            const int cs_lo = s_runstart[cbp];
            const int cs_hi = s_runstart[cbp + CHUNK] - 1;
            shade_range(cs_lo, cs_hi, tid - NPROJ, 32, cbp,
                        s_run, &s_proj[(c - 1) & 1][0][0],
                        start, ox, oy, oz, dx, dy, dz, dnorm, shm,
                        s_alpha, s_g, arow);
        }
        __syncthreads();   // closes s_proj WAR + s_coeff WAR
    }

    // epilogue: shade the last chunk with ALL threads
    if (nloops > 0) {
        const int cbl   = (nloops - 1) * CHUNK;
        const int cs_lo = s_runstart[cbl];
        shade_range(cs_lo, shi, tid, 256, cbl,
                    s_run, &s_proj[(nloops - 1) & 1][0][0],
                    start, ox, oy, oz, dx, dy, dz, dnorm, shm,
                    s_alpha, s_g, arow);
    }
    __syncthreads();

    // ---- Phase 5: serial transmittance scan (thread 0, bit-exact order) ----
    if (tid == 0 && L > 0) {
        float T = 1.0f;
        for (int s = slo; s <= shi; s++) {
            float a  = s_alpha[s];
            float ab = a * T;
            s_ab[s] = ab;
            T = __fmul_rn(T, __fadd_rn(__fsub_rn(1.0f, a), 1e-10f));
        }
    }
    __syncthreads();

    // ---- Phase 6: parallel reduction of comp / acc / depth ----
    float c0 = 0.0f, c1 = 0.0f, c2 = 0.0f, pacc = 0.0f, pdep = 0.0f;
    if (L > 0) {
        for (int s = slo + tid; s <= shi; s += 256) {
            float ab = s_ab[s];
            float ts = __fadd_rn(start, __fmul_rn((float)s, STEPF));
            c0   = fmaf(ab, s_g[s][0], c0);
            c1   = fmaf(ab, s_g[s][1], c1);
            c2   = fmaf(ab, s_g[s][2], c2);
            pacc += ab;
            pdep = fmaf(ab, ts, pdep);
        }
    }
    {
        const unsigned m = 0xFFFFFFFFu;
        #pragma unroll
        for (int o = 16; o > 0; o >>= 1) {
            c0   += __shfl_down_sync(m, c0, o);
            c1   += __shfl_down_sync(m, c1, o);
            c2   += __shfl_down_sync(m, c2, o);
            pacc += __shfl_down_sync(m, pacc, o);
            pdep += __shfl_down_sync(m, pdep, o);
        }
        int wd = tid >> 5, lane = tid & 31;
        if (lane == 0) {
            s_red[wd][0] = c0; s_red[wd][1] = c1; s_red[wd][2] = c2;
            s_red[wd][3] = pacc; s_red[wd][4] = pdep;
        }
        __syncthreads();
        if (tid == 0) {
            float t0 = 0, t1 = 0, t2 = 0, ta = 0, td = 0;
            #pragma unroll
            for (int w = 0; w < 8; w++) {
                t0 += s_red[w][0]; t1 += s_red[w][1]; t2 += s_red[w][2];
                ta += s_red[w][3]; td += s_red[w][4];
            }
            out_depth[ray] = td;
            float bg = __fsub_rn(1.0f, ta);
            out_rgb[ray * 3 + 0] = t0 + bg;
            out_rgb[ray * 3 + 1] = t1 + bg;
            out_rgb[ray * 3 + 2] = t2 + bg;
        }
    }

    // ---- Phase 7: zero masked alphas (parallel, coalesced) ----
    for (int s = tid; s < NSAMP; s += 256)
        if (s < slo || s > shi) arow[s] = 0.0f;
}

extern "C" void kernel_launch(void* const* d_in, const int* in_sizes, int n_in,
                              void* d_out, int out_size) {
    const float* rays_o = (const float*)d_in[0];
    const float* rays_d = (const float*)d_in[1];
    const float* grid   = (const float*)d_in[2];
    const float* atoms  = (const float*)d_in[3];
    // d_in[4] = grid_id (unused)
    plenoxel_kernel<<<NRAYS, 256>>>(rays_o, rays_d, grid, atoms, (float*)d_out);
}

// round 17
// speedup vs baseline: 1.0750x; 1.0442x over previous
#include <cuda_runtime.h>
#include <cstdint>

#define NRAYS   1024
#define NSAMP   767
#define NC      64
#define DATADIM 28
#define NPROJ   224   // 8 * 28, tids 0..223 = warps 0-6
#define CHUNK   12
#define NPAIR   6     // CHUNK/2 packed run-pairs
#define MAXS    768
#define RUNSTRIDE (8 * DATADIM + 4)

// RN_f32(exp(-x)) for x >= 0 -- IDENTICAL to the passing R9..R16 version.
__device__ __forceinline__ float exp_neg_rn(float x) {
    if (x < 0.0625f) {
        double r = -(double)x;
        double e = 1.0 + r * (1.0 + r * (0.5 + r * (1.0 / 6.0 + r * (1.0 / 24.0 +
                   r * (1.0 / 120.0 + r * (1.0 / 720.0 + r * (1.0 / 5040.0)))))));
        return (float)e;
    }
    return (float)exp(-(double)x);
}

// Shade samples [s0+lane : s1 : stride]; arithmetic byte-identical to R11..R16.
__device__ __forceinline__ void shade_range(
    int s0, int s1, int lane, int stride, int cb,
    const short* s_run, const float* proj,
    float start, float ox, float oy, float oz,
    float dx, float dy, float dz, float dnorm,
    const float* shm,
    float* s_alpha, float (*s_g)[3], float* arow)
{
    const float RAD    = 1.3f;
    const float STEPF  = (float)(1.3 * 2.0 / 64.0 / 2.0 / 2.0);
    const float CLIPHI = (float)(1.0 - 1e-6);
    const float TWOR   = 2.6f;

    for (int s = s0 + lane; s <= s1; s += stride) {
        float ts = __fadd_rn(start, __fmul_rn((float)s, STEPF));
        float px = __fadd_rn(ox, __fmul_rn(ts, dx));
        float py = __fadd_rn(oy, __fmul_rn(ts, dy));
        float pz = __fadd_rn(oz, __fmul_rn(ts, dz));
        float qx = fminf(fmaxf(__fdiv_rn(__fadd_rn(px, RAD), TWOR), 0.0f), CLIPHI);
        float qy = fminf(fmaxf(__fdiv_rn(__fadd_rn(py, RAD), TWOR), 0.0f), CLIPHI);
        float qz = fminf(fmaxf(__fdiv_rn(__fadd_rn(pz, RAD), TWOR), 0.0f), CLIPHI);
        float pcx = __fmul_rn(qx, 64.0f);
        float pcy = __fmul_rn(qy, 64.0f);
        float pcz = __fmul_rn(qz, 64.0f);
        float fx = floorf(pcx), fy = floorf(pcy), fz = floorf(pcz);
        float lx = __fsub_rn(pcx, fx);
        float ly = __fsub_rn(pcy, fy);
        float lz = __fsub_rn(pcz, fz);

        float w0x, w1x, w0y, w1y, w0z, w1z;
        int i0x, i1x, i0y, i1y, i0z, i1z;
        {
            float u = __fsub_rn(__fmul_rn(lx, 2.0f), 0.5f);
            float fl = floorf(u); float t = __fsub_rn(u, fl);
            int ii = (int)fl;
            i0x = min(max(ii, 0), 1); i1x = min(max(ii + 1, 0), 1);
            w0x = __fsub_rn(1.0f, t); w1x = t;
        }
        {
            float u = __fsub_rn(__fmul_rn(ly, 2.0f), 0.5f);
            float fl = floorf(u); float t = __fsub_rn(u, fl);
            int ii = (int)fl;
            i0y = min(max(ii, 0), 1); i1y = min(max(ii + 1, 0), 1);
            w0y = __fsub_rn(1.0f, t); w1y = t;
        }
        {
            float u = __fsub_rn(__fmul_rn(lz, 2.0f), 0.5f);
            float fl = floorf(u); float t = __fsub_rn(u, fl);
            int ii = (int)fl;
            i0z = min(max(ii, 0), 1); i1z = min(max(ii + 1, 0), 1);
            w0z = __fsub_rn(1.0f, t); w1z = t;
        }

        float w8[8]; int off8[8];
        {
            int idx = 0;
            #pragma unroll
            for (int kx = 0; kx < 2; kx++) {
                float wx = kx ? w1x : w0x;
                int   ix = kx ? i1x : i0x;
                #pragma unroll
                for (int ky = 0; ky < 2; ky++) {
                    float wxy = __fmul_rn(wx, ky ? w1y : w0y);
                    int   iy  = ix * 2 + (ky ? i1y : i0y);
                    #pragma unroll
                    for (int kz = 0; kz < 2; kz++) {
                        w8[idx]   = __fmul_rn(wxy, kz ? w1z : w0z);
                        off8[idx] = (iy * 2 + (kz ? i1z : i0z)) * DATADIM;
                        idx++;
                    }
                }
            }
        }

        const float* prow = proj + (s_run[s] - cb) * RUNSTRIDE;
        float r0 = 0.0f, r1 = 0.0f, r2 = 0.0f, sig_o = 0.0f;
        #pragma unroll
        for (int dg = 0; dg < 7; dg++) {
            float o0 = 0.0f, o1 = 0.0f, o2 = 0.0f, o3 = 0.0f;
            #pragma unroll
            for (int k = 0; k < 8; k++) {
                const float4 p = *(const float4*)(prow + off8[k] + dg * 4);
                o0 = __fadd_rn(o0, __fmul_rn(w8[k], p.x));
                o1 = __fadd_rn(o1, __fmul_rn(w8[k], p.y));
                o2 = __fadd_rn(o2, __fmul_rn(w8[k], p.z));
                o3 = __fadd_rn(o3, __fmul_rn(w8[k], p.w));
            }
            const int d0 = dg * 4;
            float ov[4] = {o0, o1, o2, o3};
            #pragma unroll
            for (int j = 0; j < 4; j++) {
                const int d = d0 + j;
                if (d < 9)        r0 = fmaf(ov[j], shm[d], r0);
                else if (d < 18)  r1 = fmaf(ov[j], shm[d - 9], r1);
                else if (d < 27)  r2 = fmaf(ov[j], shm[d - 18], r2);
                else              sig_o = ov[j];
            }
        }

        // alpha path -- bit-identical to R9..R16
        float sigma = fmaxf(sig_o, 0.0f);
        float ts1   = __fadd_rn(start, __fmul_rn((float)(s + 1), STEPF));
        float dist  = __fmul_rn(__fsub_rn(ts1, ts), dnorm);
        float x     = __fmul_rn(sigma, dist);
        float e     = exp_neg_rn(x);
        float alpha = __fsub_rn(1.0f, e);
        s_alpha[s] = alpha;
        arow[s]    = alpha;

        s_g[s][0] = 1.0f / (1.0f + expf(-r0));
        s_g[s][1] = 1.0f / (1.0f + expf(-r1));
        s_g[s][2] = 1.0f / (1.0f + expf(-r2));
    }
}

__global__ void __launch_bounds__(256, 4) plenoxel_kernel(
    const float* __restrict__ rays_o,
    const float* __restrict__ rays_d,
    const float* __restrict__ grid,
    const float* __restrict__ atoms,
    float* __restrict__ out)
{
    const float RAD    = 1.3f;
    const float STEPF  = (float)(1.3 * 2.0 / 64.0 / 2.0 / 2.0);
    const float CLIPHI = (float)(1.0 - 1e-6);
    const float TWOR   = 2.6f;

    const int ray = blockIdx.x;
    const int tid = threadIdx.x;
    if (ray >= NRAYS) return;

    // s_coeff2[a][r]: run-major-in-pairs transposed coeff. Row = 12 floats
    // (48 B, 16B-aligned) -> 3 x ulonglong2 loads yield 6 pre-packed run-pairs.
    __shared__ __align__(16) float s_coeff2[NC][CHUNK];         // 3 KB
    __shared__ __align__(16) float s_proj[2][CHUNK][RUNSTRIDE]; // 21.9 KB
    __shared__ int   s_clin[MAXS];
    __shared__ short s_run[MAXS];
    __shared__ short s_runstart[MAXS];
    __shared__ int   s_runclin[MAXS];
    __shared__ float s_alpha[MAXS];
    __shared__ float s_g[MAXS][3];
    __shared__ float s_red[8][8];
    __shared__ unsigned s_bits[24];
    __shared__ int   s_cnt[24], s_cbase[24];
    __shared__ int   s_slo, s_shi, s_nruns;

    float* s_ab = (float*)s_clin;        // s_clin dead after RLE

    float* out_rgb   = out;
    float* out_alpha = out + NRAYS * 3;
    float* out_depth = out + NRAYS * 3 + NRAYS * NSAMP;
    float* arow      = out_alpha + ray * NSAMP;

    const float ox = rays_o[ray * 3 + 0];
    const float oy = rays_o[ray * 3 + 1];
    const float oz = rays_o[ray * 3 + 2];
    const float dx = rays_d[ray * 3 + 0];
    const float dy = rays_d[ray * 3 + 1];
    const float dz = rays_d[ray * 3 + 2];

    float start;
    {
        float ax = fminf(__fdiv_rn(__fsub_rn(RAD, ox), dx), __fdiv_rn(__fsub_rn(-RAD, ox), dx));
        float ay = fminf(__fdiv_rn(__fsub_rn(RAD, oy), dy), __fdiv_rn(__fsub_rn(-RAD, oy), dy));
        float az = fminf(__fdiv_rn(__fsub_rn(RAD, oz), dz), __fdiv_rn(__fsub_rn(-RAD, oz), dz));
        start = fmaxf(fmaxf(ax, ay), az);
    }
    const float dnorm = sqrtf(__fadd_rn(__fadd_rn(__fmul_rn(dx, dx), __fmul_rn(dy, dy)),
                                        __fmul_rn(dz, dz)));

    float shm[9];
    {
        float x = __fdiv_rn(dx, dnorm), y = __fdiv_rn(dy, dnorm), z = __fdiv_rn(dz, dnorm);
        shm[0] = 0.28209479177387814f;
        shm[1] = -0.4886025119029199f * y;
        shm[2] =  0.4886025119029199f * z;
        shm[3] = -0.4886025119029199f * x;
        shm[4] =  1.0925484305920792f * x * y;
        shm[5] = -1.0925484305920792f * y * z;
        shm[6] =  0.31539156525252005f * (2.0f * z * z - x * x - y * y);
        shm[7] = -1.0925484305920792f * x * z;
        shm[8] =  0.5462742152960396f * (x * x - y * y);
    }

    // ---- Phase 1+2 ----
    if (tid == 0) { s_slo = 0x7FFFFFFF; s_shi = -1; }
    __syncthreads();

    for (int s = tid; s < NSAMP; s += 256) {
        float ts = __fadd_rn(start, __fmul_rn((float)s, STEPF));
        float px = __fadd_rn(ox, __fmul_rn(ts, dx));
        float py = __fadd_rn(oy, __fmul_rn(ts, dy));
        float pz = __fadd_rn(oz, __fmul_rn(ts, dz));
        bool mask = (px > -RAD) && (px < RAD) &&
                    (py > -RAD) && (py < RAD) &&
                    (pz > -RAD) && (pz < RAD);
        if (mask) {
            atomicMin(&s_slo, s);
            atomicMax(&s_shi, s);
            float qx = fminf(fmaxf(__fdiv_rn(__fadd_rn(px, RAD), TWOR), 0.0f), CLIPHI);
            float qy = fminf(fmaxf(__fdiv_rn(__fadd_rn(py, RAD), TWOR), 0.0f), CLIPHI);
            float qz = fminf(fmaxf(__fdiv_rn(__fadd_rn(pz, RAD), TWOR), 0.0f), CLIPHI);
            int cx = (int)floorf(__fmul_rn(qx, 64.0f));
            int cy = (int)floorf(__fmul_rn(qy, 64.0f));
            int cz = (int)floorf(__fmul_rn(qz, 64.0f));
            s_clin[s] = (cx * 64 + cy) * 64 + cz;
        }
    }
    __syncthreads();

    const int slo = s_slo, shi = s_shi;
    const int L = (shi >= slo) ? (shi - slo + 1) : 0;
    const int nchunks32 = (L + 31) >> 5;

    // ---- Phase 3: parallel RLE ----
    for (int i = tid; i < nchunks32 * 32; i += 256) {
        int lane = i & 31, chunk = i >> 5;
        bool flag = false;
        if (i < L) {
            int s = slo + i;
            flag = (i == 0) || (s_clin[s] != s_clin[s - 1]);
        }
        unsigned b = __ballot_sync(0xFFFFFFFFu, flag);
        if (lane == 0) { s_bits[chunk] = b; s_cnt[chunk] = __popc(b); }
    }
    __syncthreads();
    if (tid == 0) {
        int acc = 0;
        for (int c = 0; c < nchunks32; c++) { s_cbase[c] = acc; acc += s_cnt[c]; }
        s_nruns = acc;
    }
    __syncthreads();
    for (int i = tid; i < L; i += 256) {
        int s = slo + i;
        int lane = i & 31, chunk = i >> 5;
        unsigned b = s_bits[chunk];
        int idx = s_cbase[chunk] + __popc(b & ((1u << lane) - 1u));
        int flag = (b >> lane) & 1u;
        if (flag) { s_runclin[idx] = s_clin[s]; s_runstart[idx] = (short)s; }
        s_run[s] = (short)(idx + flag - 1);
    }
    __syncthreads();

    const int nruns  = s_nruns;
    const int nloops = (nruns + CHUNK - 1) / CHUNK;

    // ---- Phase 4: warp-specialized pipeline, packed-FFMA2 projection ----
    // pre[5] covers CHUNK*NC = 768 <= 5*224; zero-fill beyond nr_c so packed
    // lanes for absent runs compute harmless zeros.
    float pre[5];
    if (tid < NPROJ && nloops > 0) {
        const int nr0 = min(CHUNK, nruns);
        #pragma unroll
        for (int j = 0; j < 5; j++) {
            int idx = tid + j * NPROJ;
            if (idx < CHUNK * NC) {
                int r = idx >> 6;
                pre[j] = (r < nr0) ? grid[(long long)s_runclin[r] * NC + (idx & 63)] : 0.0f;
            }
        }
    }

    const int pf = tid / DATADIM;
    const int pd = tid - pf * DATADIM;

    for (int c = 0; c < nloops; c++) {
        const int cb = c * CHUNK;
        const int nr_c = min(CHUNK, nruns - cb);

        if (tid < NPROJ) {
            // commit prefetched coeff TRANSPOSED: s_coeff2[a][r]
            #pragma unroll
            for (int j = 0; j < 5; j++) {
                int idx = tid + j * NPROJ;
                if (idx < CHUNK * NC)
                    s_coeff2[idx & 63][idx >> 6] = pre[j];
            }
            asm volatile("bar.sync 1, 224;" ::: "memory");

            // prefetch next chunk
            const int nb = cb + CHUNK;
            if (nb < nruns) {
                const int nrn = min(CHUNK, nruns - nb);
                #pragma unroll
                for (int j = 0; j < 5; j++) {
                    int idx = tid + j * NPROJ;
                    if (idx < CHUNK * NC) {
                        int r = idx >> 6;
                        pre[j] = (r < nrn) ? grid[(long long)s_runclin[nb + r] * NC + (idx & 63)] : 0.0f;
                    }
                }
            }

            // projection: run-pair packed FFMA2. Each 32-bit lane of acc2[p]
            // is an independent sequential a=0..63 RN-FMA chain for run 2p /
            // 2p+1 -- bit-identical to the scalar chain (sigma included).
            const float* __restrict__ acol = atoms + (pf * NC) * DATADIM + pd;
            unsigned long long acc2[NPAIR];
            #pragma unroll
            for (int p = 0; p < NPAIR; p++) acc2[p] = 0ull;
            #pragma unroll 4
            for (int a4 = 0; a4 < NC / 4; a4++) {
                float av0 = __ldg(acol + (a4 * 4 + 0) * DATADIM);
                float av1 = __ldg(acol + (a4 * 4 + 1) * DATADIM);
                float av2 = __ldg(acol + (a4 * 4 + 2) * DATADIM);
                float av3 = __ldg(acol + (a4 * 4 + 3) * DATADIM);
                unsigned long long ap0, ap1, ap2, ap3;
                asm("mov.b64 %0, {%1, %1};" : "=l"(ap0) : "f"(av0));
                asm("mov.b64 %0, {%1, %1};" : "=l"(ap1) : "f"(av1));
                asm("mov.b64 %0, {%1, %1};" : "=l"(ap2) : "f"(av2));
                asm("mov.b64 %0, {%1, %1};" : "=l"(ap3) : "f"(av3));
                #pragma unroll
                for (int q = 0; q < 4; q++) {
                    const int a = a4 * 4 + q;
                    unsigned long long ap = (q == 0) ? ap0 : (q == 1) ? ap1 : (q == 2) ? ap2 : ap3;
                    const ulonglong2* row = (const ulonglong2*)&s_coeff2[a][0];
                    ulonglong2 c01 = row[0];   // run-pairs 0,1
                    ulonglong2 c23 = row[1];   // run-pairs 2,3
                    ulonglong2 c45 = row[2];   // run-pairs 4,5
                    asm("fma.rn.f32x2 %0, %1, %2, %0;" : "+l"(acc2[0]) : "l"(c01.x), "l"(ap));
                    asm("fma.rn.f32x2 %0, %1, %2, %0;" : "+l"(acc2[1]) : "l"(c01.y), "l"(ap));
                    asm("fma.rn.f32x2 %0, %1, %2, %0;" : "+l"(acc2[2]) : "l"(c23.x), "l"(ap));
                    asm("fma.rn.f32x2 %0, %1, %2, %0;" : "+l"(acc2[3]) : "l"(c23.y), "l"(ap));
                    asm("fma.rn.f32x2 %0, %1, %2, %0;" : "+l"(acc2[4]) : "l"(c45.x), "l"(ap));
                    asm("fma.rn.f32x2 %0, %1, %2, %0;" : "+l"(acc2[5]) : "l"(c45.y), "l"(ap));
                }
            }
            #pragma unroll
            for (int p = 0; p < NPAIR; p++) {
                float lo, hi;
                asm("mov.b64 {%0, %1}, %2;" : "=f"(lo), "=f"(hi) : "l"(acc2[p]));
                if (2 * p < nr_c)     s_proj[c & 1][2 * p][pf * DATADIM + pd]     = lo;
                if (2 * p + 1 < nr_c) s_proj[c & 1][2 * p + 1][pf * DATADIM + pd] = hi;
            }
        } else if (c > 0) {
            const int cbp   = cb - CHUNK;
            const int cs_lo = s_runstart[cbp];
            const int cs_hi = s_runstart[cbp + CHUNK] - 1;
            shade_range(cs_lo, cs_hi, tid - NPROJ, 32, cbp,
                        s_run, &s_proj[(c - 1) & 1][0][0],
                        start, ox, oy, oz, dx, dy, dz, dnorm, shm,
                        s_alpha, s_g, arow);
        }
        __syncthreads();
    }

    // epilogue: shade the last chunk with ALL threads
    if (nloops > 0) {
        const int cbl   = (nloops - 1) * CHUNK;
        const int cs_lo = s_runstart[cbl];
        shade_range(cs_lo, shi, tid, 256, cbl,
                    s_run, &s_proj[(nloops - 1) & 1][0][0],
                    start, ox, oy, oz, dx, dy, dz, dnorm, shm,
                    s_alpha, s_g, arow);
    }
    __syncthreads();

    // ---- Phase 5: serial transmittance scan (thread 0, bit-exact order) ----
    if (tid == 0 && L > 0) {
        float T = 1.0f;
        for (int s = slo; s <= shi; s++) {
            float a  = s_alpha[s];
            float ab = a * T;
            s_ab[s] = ab;
            T = __fmul_rn(T, __fadd_rn(__fsub_rn(1.0f, a), 1e-10f));
        }
    }
    __syncthreads();

    // ---- Phase 6: parallel reduction of comp / acc / depth ----
    float c0 = 0.0f, c1 = 0.0f, c2 = 0.0f, pacc = 0.0f, pdep = 0.0f;
    if (L > 0) {
        for (int s = slo + tid; s <= shi; s += 256) {
            float ab = s_ab[s];
            float ts = __fadd_rn(start, __fmul_rn((float)s, STEPF));
            c0   = fmaf(ab, s_g[s][0], c0);
            c1   = fmaf(ab, s_g[s][1], c1);
            c2   = fmaf(ab, s_g[s][2], c2);
            pacc += ab;
            pdep = fmaf(ab, ts, pdep);
        }
    }
    {
        const unsigned m = 0xFFFFFFFFu;
        #pragma unroll
        for (int o = 16; o > 0; o >>= 1) {
            c0   += __shfl_down_sync(m, c0, o);
            c1   += __shfl_down_sync(m, c1, o);
            c2   += __shfl_down_sync(m, c2, o);
            pacc += __shfl_down_sync(m, pacc, o);
            pdep += __shfl_down_sync(m, pdep, o);
        }
        int wd = tid >> 5, lane = tid & 31;
        if (lane == 0) {
            s_red[wd][0] = c0; s_red[wd][1] = c1; s_red[wd][2] = c2;
            s_red[wd][3] = pacc; s_red[wd][4] = pdep;
        }
        __syncthreads();
        if (tid == 0) {
            float t0 = 0, t1 = 0, t2 = 0, ta = 0, td = 0;
            #pragma unroll
            for (int w = 0; w < 8; w++) {
                t0 += s_red[w][0]; t1 += s_red[w][1]; t2 += s_red[w][2];
                ta += s_red[w][3]; td += s_red[w][4];
            }
            out_depth[ray] = td;
            float bg = __fsub_rn(1.0f, ta);
            out_rgb[ray * 3 + 0] = t0 + bg;
            out_rgb[ray * 3 + 1] = t1 + bg;
            out_rgb[ray * 3 + 2] = t2 + bg;
        }
    }

    // ---- Phase 7: zero masked alphas (parallel, coalesced) ----
    for (int s = tid; s < NSAMP; s += 256)
        if (s < slo || s > shi) arow[s] = 0.0f;
}

extern "C" void kernel_launch(void* const* d_in, const int* in_sizes, int n_in,
                              void* d_out, int out_size) {
    const float* rays_o = (const float*)d_in[0];
    const float* rays_d = (const float*)d_in[1];
    const float* grid   = (const float*)d_in[2];
    const float* atoms  = (const float*)d_in[3];
    // d_in[4] = grid_id (unused)
    plenoxel_kernel<<<NRAYS, 256>>>(rays_o, rays_d, grid, atoms, (float*)d_out);
}